// round 17
// baseline (speedup 1.0000x reference)
#include <cuda_runtime.h>

// predictions [8,19,512,1024] f32, targets [8,512,1024] i32, output: scalar f32.
#define NB        8
#define NC        19
#define NPB       (512 * 1024)
#define LOG2_NPB  19
#define THRESH    0.7f
#define NMIN      10000

#define TPB       256
#define PIX_PER_T 8
#define NBLOCKS   ((NB * NPB) / (TPB * PIX_PER_T))   // 2048

__device__ double       g_sum[NB];
__device__ int          g_cnt[NB];
__device__ unsigned int g_done;

// CE loss recompute, exact f32 (rare exact-top-k fallback path only).
__device__ __forceinline__ float pixel_loss(const float* __restrict__ pred,
                                            const int*   __restrict__ tgt,
                                            int b, int i) {
    const int t = tgt[b * NPB + i];
    float s = 0.f, xt = 0.f;
#pragma unroll
    for (int c = 0; c < NC; c++) {
        const float v = pred[(b * NC + c) * NPB + i];
        s += __expf(v);
        if (c == t) xt = v;
    }
    float l = __logf(s) - xt;
    return l < 0.f ? 0.f : l;
}

__global__ void __launch_bounds__(TPB)
ohem_fused(const float* __restrict__ pred,
           const int*   __restrict__ tgt,
           float*       __restrict__ out) {
    // ---------------- phase 1: lean streaming CE, 8 px/thread --------------
    const int tid8 = blockIdx.x * TPB + threadIdx.x;   // 8-pixel group id
    const int pix  = tid8 << 3;
    const int b    = pix >> LOG2_NPB;                  // uniform within a block
    const int n    = pix & (NPB - 1);

    // Targets: never re-read -> evict-first.
    const int4 ta = __ldcs(reinterpret_cast<const int4*>(tgt + pix));
    const int4 tb = __ldcs(reinterpret_cast<const int4*>(tgt + pix) + 1);

    const float4* p4       = reinterpret_cast<const float4*>(pred);
    const int     cstride4 = NPB / 4;
    const int     base4    = b * NC * cstride4 + (n >> 2);

    // TWO independent LDG.128 per channel iteration -> doubled per-thread MLP
    // (the one variable that separates the 6.1TB/s runs from the 5.6 ones).
    // .cg: L1-bypass, L2-resident so the late gathers below hit L2.
    float4 sa = make_float4(0.f, 0.f, 0.f, 0.f);
    float4 sb = make_float4(0.f, 0.f, 0.f, 0.f);
#pragma unroll
    for (int c = 0; c < NC; c++) {
        const float4 va = __ldcg(&p4[base4 + c * cstride4]);
        const float4 vb = __ldcg(&p4[base4 + c * cstride4 + 1]);
        sa.x += __expf(va.x);
        sa.y += __expf(va.y);
        sa.z += __expf(va.z);
        sa.w += __expf(va.w);
        sb.x += __expf(vb.x);
        sb.y += __expf(vb.y);
        sb.z += __expf(vb.z);
        sb.w += __expf(vb.w);
    }

    // Target-logit gathers AFTER the stream (lines L2-resident), no L1 alloc.
    const int base_e = b * (NC * NPB) + n;
    float l0 = __logf(sa.x) - __ldcg(pred + base_e + ta.x * NPB + 0);
    float l1 = __logf(sa.y) - __ldcg(pred + base_e + ta.y * NPB + 1);
    float l2 = __logf(sa.z) - __ldcg(pred + base_e + ta.z * NPB + 2);
    float l3 = __logf(sa.w) - __ldcg(pred + base_e + ta.w * NPB + 3);
    float l4 = __logf(sb.x) - __ldcg(pred + base_e + tb.x * NPB + 4);
    float l5 = __logf(sb.y) - __ldcg(pred + base_e + tb.y * NPB + 5);
    float l6 = __logf(sb.z) - __ldcg(pred + base_e + tb.z * NPB + 6);
    float l7 = __logf(sb.w) - __ldcg(pred + base_e + tb.w * NPB + 7);

    float ls = 0.f;
    int   lc = 0;
    if (l0 > THRESH) { ls += l0; lc++; }
    if (l1 > THRESH) { ls += l1; lc++; }
    if (l2 > THRESH) { ls += l2; lc++; }
    if (l3 > THRESH) { ls += l3; lc++; }
    if (l4 > THRESH) { ls += l4; lc++; }
    if (l5 > THRESH) { ls += l5; lc++; }
    if (l6 > THRESH) { ls += l6; lc++; }
    if (l7 > THRESH) { ls += l7; lc++; }

#pragma unroll
    for (int o = 16; o; o >>= 1) {
        ls += __shfl_down_sync(0xffffffffu, ls, o);
        lc += __shfl_down_sync(0xffffffffu, lc, o);
    }

    __shared__ float        sh_f[TPB / 32];
    __shared__ int          sh_i[TPB / 32];
    __shared__ unsigned int sh_last;

    const int w = threadIdx.x >> 5, lane = threadIdx.x & 31;
    if (lane == 0) { sh_f[w] = ls; sh_i[w] = lc; }
    __syncthreads();

    if (threadIdx.x == 0) {
        double S = 0.0; int Cn = 0;
#pragma unroll
        for (int i = 0; i < TPB / 32; i++) { S += (double)sh_f[i]; Cn += sh_i[i]; }
        atomicAdd(&g_sum[b], S);
        atomicAdd(&g_cnt[b], Cn);
        __threadfence();
        const unsigned int tk = atomicAdd(&g_done, 1u);
        sh_last = (tk == (unsigned)(NBLOCKS - 1)) ? 1u : 0u;
    }
    __syncthreads();
    if (!sh_last) return;

    // ---------------- phase 2: finalize (last block only) ------------------
    __threadfence();

    __shared__ unsigned int hist[256];
    __shared__ unsigned int s_prefix;
    __shared__ int          s_k;
    __shared__ double       sh_d2[TPB / 32];
    __shared__ int          sh_i2[TPB / 32];
    __shared__ double       s_acc;

    if (threadIdx.x == 0) s_acc = 0.0;
    __syncthreads();

    for (int bb = 0; bb < NB; bb++) {
        const int    cnt = g_cnt[bb];
        const double sum = g_sum[bb];

        if (cnt >= NMIN) {
            if (threadIdx.x == 0) s_acc += sum / (double)cnt;
            __syncthreads();
        } else {
            // Exact top-NMIN via 4-pass MSB radix select (dead on this input).
            if (threadIdx.x == 0) { s_prefix = 0u; s_k = NMIN; }
            __syncthreads();
            for (int pass = 0; pass < 4; pass++) {
                const int shift = 24 - pass * 8;
                for (int i = threadIdx.x; i < 256; i += TPB) hist[i] = 0u;
                __syncthreads();
                const unsigned prefix  = s_prefix;
                const unsigned mask_hi = (pass == 0) ? 0u
                                       : (0xFFFFFFFFu << (shift + 8));
                for (int i = threadIdx.x; i < NPB; i += TPB) {
                    const unsigned u = __float_as_uint(pixel_loss(pred, tgt, bb, i));
                    if ((u & mask_hi) == prefix)
                        atomicAdd(&hist[(u >> shift) & 255u], 1u);
                }
                __syncthreads();
                if (threadIdx.x == 0) {
                    int kk = s_k;
                    int d  = 255;
                    while (d > 0 && (int)hist[d] < kk) { kk -= (int)hist[d]; d--; }
                    s_prefix = prefix | ((unsigned)d << shift);
                    s_k      = kk;
                }
                __syncthreads();
            }
            const float pivot = __uint_as_float(s_prefix);
            double fs = 0.0; int fg = 0;
            for (int i = threadIdx.x; i < NPB; i += TPB) {
                const float vv = pixel_loss(pred, tgt, bb, i);
                if (vv > pivot) { fs += (double)vv; fg++; }
            }
#pragma unroll
            for (int o = 16; o; o >>= 1) {
                fs += __shfl_down_sync(0xffffffffu, fs, o);
                fg += __shfl_down_sync(0xffffffffu, fg, o);
            }
            if (lane == 0) { sh_d2[w] = fs; sh_i2[w] = fg; }
            __syncthreads();
            if (threadIdx.x == 0) {
                double S = 0.0; int G = 0;
#pragma unroll
                for (int i = 0; i < TPB / 32; i++) { S += sh_d2[i]; G += sh_i2[i]; }
                const double kept = S + (double)(NMIN - G) * (double)pivot;
                s_acc += kept / (double)NMIN;
            }
            __syncthreads();
        }
    }

    if (threadIdx.x == 0) {
        out[0] = (float)(s_acc / (double)NB);
#pragma unroll
        for (int i = 0; i < NB; i++) { g_sum[i] = 0.0; g_cnt[i] = 0; }
        g_done = 0u;
        __threadfence();
    }
}

extern "C" void kernel_launch(void* const* d_in, const int* in_sizes, int n_in,
                              void* d_out, int out_size) {
    const float* pred = (const float*)d_in[0];
    const int*   tgt  = (const int*)d_in[1];
    float*       out  = (float*)d_out;

    ohem_fused<<<NBLOCKS, TPB>>>(pred, tgt, out);
}